// round 1
// baseline (speedup 1.0000x reference)
#include <cuda_runtime.h>
#include <math.h>

// Problem constants
#define BN_WIN   4096
#define NTOK     64
#define DIMC     384
#define NHEAD    12
#define HEADD    32
#define QKVD     1152   // 3*DIMC

// Scratch (device globals — no runtime allocation allowed)
__device__ float g_qkv[(size_t)BN_WIN * NTOK * QKVD];   // [Bn*64, 1152]
__device__ float g_att[(size_t)BN_WIN * NTOK * DIMC];   // [Bn*64, 384]

// ---------------------------------------------------------------------------
// NT SGEMM: C[M,N] = A[M,K] @ B[N,K]^T + bias[N]
// A row-major stride K, B row-major stride K, C row-major stride ldc.
// Block tile 128x128, K-step 8, 256 threads, 8x8 register tile per thread.
// grid.x = N/128, grid.y = M/128. All dims divide evenly here.
// ---------------------------------------------------------------------------
__global__ __launch_bounds__(256) void sgemm_nt(
    const float* __restrict__ A, const float* __restrict__ B,
    const float* __restrict__ bias, float* __restrict__ C,
    int K, int ldc)
{
    __shared__ float As[8][128];
    __shared__ float Bs[8][128];

    const int t    = threadIdx.x;
    const int lrow = t >> 1;            // 0..127 (row within tile for loads)
    const int lkq  = (t & 1) * 4;       // 0 or 4 (k quad for loads)
    const int tx   = t & 15;            // 0..15  -> col group
    const int ty   = t >> 4;            // 0..15  -> row group

    const float* Ablk = A + (size_t)(blockIdx.y) * 128 * K;
    const float* Bblk = B + (size_t)(blockIdx.x) * 128 * K;

    float c[8][8];
#pragma unroll
    for (int m = 0; m < 8; m++)
#pragma unroll
        for (int n = 0; n < 8; n++) c[m][n] = 0.0f;

    for (int k0 = 0; k0 < K; k0 += 8) {
        float4 av = *(const float4*)(Ablk + (size_t)lrow * K + k0 + lkq);
        float4 bv = *(const float4*)(Bblk + (size_t)lrow * K + k0 + lkq);
        As[lkq + 0][lrow] = av.x;
        As[lkq + 1][lrow] = av.y;
        As[lkq + 2][lrow] = av.z;
        As[lkq + 3][lrow] = av.w;
        Bs[lkq + 0][lrow] = bv.x;
        Bs[lkq + 1][lrow] = bv.y;
        Bs[lkq + 2][lrow] = bv.z;
        Bs[lkq + 3][lrow] = bv.w;
        __syncthreads();

#pragma unroll
        for (int kk = 0; kk < 8; kk++) {
            float a[8], b[8];
            *(float4*)&a[0] = *(const float4*)&As[kk][ty * 8];
            *(float4*)&a[4] = *(const float4*)&As[kk][ty * 8 + 4];
            *(float4*)&b[0] = *(const float4*)&Bs[kk][tx * 8];
            *(float4*)&b[4] = *(const float4*)&Bs[kk][tx * 8 + 4];
#pragma unroll
            for (int m = 0; m < 8; m++)
#pragma unroll
                for (int n = 0; n < 8; n++)
                    c[m][n] += a[m] * b[n];
        }
        __syncthreads();
    }

    const int colbase = blockIdx.x * 128 + tx * 8;
    float4 bv0 = *(const float4*)(bias + colbase);
    float4 bv1 = *(const float4*)(bias + colbase + 4);

#pragma unroll
    for (int m = 0; m < 8; m++) {
        const int row = blockIdx.y * 128 + ty * 8 + m;
        float* Crow = C + (size_t)row * ldc + colbase;
        float4 o0, o1;
        o0.x = c[m][0] + bv0.x; o0.y = c[m][1] + bv0.y;
        o0.z = c[m][2] + bv0.z; o0.w = c[m][3] + bv0.w;
        o1.x = c[m][4] + bv1.x; o1.y = c[m][5] + bv1.y;
        o1.z = c[m][6] + bv1.z; o1.w = c[m][7] + bv1.w;
        *(float4*)(Crow)     = o0;
        *(float4*)(Crow + 4) = o1;
    }
}

// ---------------------------------------------------------------------------
// Fused window attention (per window, per head): softmax(q k^T * scale + bias) v
// block = (window b = blockIdx.x, head h = blockIdx.y), 64 threads, thread i =
// query row. q/k/v staged in smem; scores kept in registers (fully unrolled).
// Relative-position bias index computed inline:
//   idx(i,j) = ((i/8 - j/8) + 7)*15 + ((i%8 - j%8) + 7);  bias_table[idx*12+h]
// ---------------------------------------------------------------------------
__global__ __launch_bounds__(64) void attn_kernel(const float* __restrict__ bias_table)
{
    const int b = blockIdx.x;
    const int h = blockIdx.y;
    const int tid = threadIdx.x;

    __shared__ float q_s[64][32];   // reused as output staging
    __shared__ float k_s[64][32];
    __shared__ float v_s[64][32];
    __shared__ float bt_s[225 * 12];

    const float* qkvw = g_qkv + (size_t)b * NTOK * QKVD;

#pragma unroll
    for (int r = 0; r < 32; r++) {         // 64*32 / 64 threads = 32 iters
        int e = r * 64 + tid;
        int j = e >> 5, d = e & 31;
        q_s[j][d] = qkvw[(size_t)j * QKVD + h * HEADD + d];
        k_s[j][d] = qkvw[(size_t)j * QKVD + DIMC + h * HEADD + d];
        v_s[j][d] = qkvw[(size_t)j * QKVD + 2 * DIMC + h * HEADD + d];
    }
    for (int e = tid; e < 225 * 12; e += 64) bt_s[e] = bias_table[e];
    __syncthreads();

    const int i = tid;
    const float scale = 0.17677669529663687f;  // 32^-0.5

    float qi[32];
#pragma unroll
    for (int d = 0; d < 32; d++) qi[d] = q_s[i][d] * scale;

    const int ri = i >> 3, ci = i & 7;

    float s[64];
    float mx = -INFINITY;
#pragma unroll
    for (int j = 0; j < 64; j++) {
        float acc = 0.0f;
#pragma unroll
        for (int d = 0; d < 32; d++) acc += qi[d] * k_s[j][d];
        const int rj = j >> 3, cj = j & 7;
        acc += bt_s[((ri - rj + 7) * 15 + (ci - cj + 7)) * 12 + h];
        s[j] = acc;
        mx = fmaxf(mx, acc);
    }

    float sum = 0.0f;
#pragma unroll
    for (int j = 0; j < 64; j++) {
        s[j] = __expf(s[j] - mx);
        sum += s[j];
    }
    const float inv = 1.0f / sum;

    // out row i: o[d] = inv * sum_j s[j] * v[j][d]   (stage into q_s[i][:])
#pragma unroll
    for (int d = 0; d < 32; d++) {
        float o = 0.0f;
#pragma unroll
        for (int j = 0; j < 64; j++) o += s[j] * v_s[j][d];
        q_s[i][d] = o * inv;
    }
    __syncthreads();

    float* outp = g_att + (size_t)b * NTOK * DIMC;
#pragma unroll
    for (int r = 0; r < 32; r++) {
        int e = r * 64 + tid;
        int j = e >> 5, d = e & 31;
        outp[(size_t)j * DIMC + h * HEADD + d] = q_s[j][d];
    }
}

// ---------------------------------------------------------------------------
// Launch
// Inputs (metadata order): x, qkv_w, qkv_b, proj_w, proj_b, bias_table
// ---------------------------------------------------------------------------
extern "C" void kernel_launch(void* const* d_in, const int* in_sizes, int n_in,
                              void* d_out, int out_size)
{
    const float* x          = (const float*)d_in[0];
    const float* qkv_w      = (const float*)d_in[1];
    const float* qkv_b      = (const float*)d_in[2];
    const float* proj_w     = (const float*)d_in[3];
    const float* proj_b     = (const float*)d_in[4];
    const float* bias_table = (const float*)d_in[5];
    float* out = (float*)d_out;

    float* qkv_ptr = nullptr;
    float* att_ptr = nullptr;
    cudaGetSymbolAddress((void**)&qkv_ptr, g_qkv);
    cudaGetSymbolAddress((void**)&att_ptr, g_att);

    const int M = BN_WIN * NTOK;   // 262144

    // 1) QKV GEMM: [M,1152] = x[M,384] @ qkv_w[1152,384]^T + qkv_b
    {
        dim3 grid(QKVD / 128, M / 128);   // (9, 2048)
        sgemm_nt<<<grid, 256>>>(x, qkv_w, qkv_b, qkv_ptr, DIMC, QKVD);
    }

    // 2) Attention per (window, head)
    {
        dim3 grid(BN_WIN, NHEAD);
        attn_kernel<<<grid, 64>>>(bias_table);
    }

    // 3) Proj GEMM: out[M,384] = g_att[M,384] @ proj_w[384,384]^T + proj_b
    {
        dim3 grid(DIMC / 128, M / 128);   // (3, 2048)
        sgemm_nt<<<grid, 256>>>(att_ptr, proj_w, proj_b, out, DIMC, DIMC);
    }
}

// round 3
// speedup vs baseline: 2.1206x; 2.1206x over previous
#include <cuda_runtime.h>
#include <cuda_bf16.h>
#include <cstdint>
#include <math.h>

#define BN_WIN 4096
#define NTOK   64
#define DIMC   384
#define NHEAD  12
#define HEADD  32
#define QKVD   1152
#define MTOT   (BN_WIN * NTOK)   // 262144
#define KCAT   1152              // 3*DIMC concatenated-K for split-bf16
#define NSTG   36                // KCAT / 32

// ---------------- scratch (device globals; no runtime alloc allowed) -------
__device__ float         g_qkv[(size_t)MTOT * QKVD];    // fp32 QKV (1.2 GB)
__device__ __nv_bfloat16 g_xcat[(size_t)MTOT * KCAT];   // [xhi | xlo | xhi]
__device__ __nv_bfloat16 g_acat[(size_t)MTOT * KCAT];   // [ahi | alo | ahi]
__device__ __nv_bfloat16 g_wqcat[(size_t)QKVD * KCAT];  // [whi | whi | wlo]
__device__ __nv_bfloat16 g_wpcat[(size_t)DIMC * KCAT];  // [whi | whi | wlo]
__device__ float         g_biasx[NHEAD * NTOK * NTOK];  // expanded rel-pos bias

// ---------------- helpers ---------------------------------------------------
__device__ __forceinline__ uint32_t smem_u32(const void* p) {
    uint32_t a;
    asm("{ .reg .u64 t; cvta.to.shared.u64 t, %1; cvt.u32.u64 %0, t; }" : "=r"(a) : "l"(p));
    return a;
}
__device__ __forceinline__ void ldsm_x4(uint32_t* r, uint32_t addr) {
    asm volatile("ldmatrix.sync.aligned.m8n8.x4.shared.b16 {%0,%1,%2,%3}, [%4];"
        : "=r"(r[0]), "=r"(r[1]), "=r"(r[2]), "=r"(r[3]) : "r"(addr));
}
__device__ __forceinline__ void mma_bf16(float* d, const uint32_t* a, const uint32_t* b) {
    asm volatile("mma.sync.aligned.m16n8k16.row.col.f32.bf16.bf16.f32 "
        "{%0,%1,%2,%3}, {%4,%5,%6,%7}, {%8,%9}, {%0,%1,%2,%3};"
        : "+f"(d[0]), "+f"(d[1]), "+f"(d[2]), "+f"(d[3])
        : "r"(a[0]), "r"(a[1]), "r"(a[2]), "r"(a[3]), "r"(b[0]), "r"(b[1]));
}
#define CP_ASYNC16(dst, src) \
    asm volatile("cp.async.cg.shared.global [%0], [%1], 16;" :: "r"(dst), "l"(src) : "memory")
#define CP_COMMIT()  asm volatile("cp.async.commit_group;" ::: "memory")
#define CP_WAIT0()   asm volatile("cp.async.wait_group 0;" ::: "memory")

// ---------------------------------------------------------------------------
// HMMA NT GEMM, K = KCAT fixed: C[M,N] = A[M,K] @ B[N,K]^T + bias[N], fp32 out
// Block 128x128, 8 warps (2x4, warp tile 64x32), k-step 32, double-buffered
// cp.async, XOR-swizzled smem (chunk ^ ((row>>1)&3)) -> conflict-free ldmatrix.
// grid.x = N/128, grid.y = M/128.
// ---------------------------------------------------------------------------
__device__ __forceinline__ void load_stage(
    const __nv_bfloat16* Ab, const __nv_bfloat16* Bb, int k0,
    uint32_t sAdst, uint32_t sBdst, int t)
{
    const int row  = t >> 1;
    const int half = t & 1;
    const __nv_bfloat16* ga = Ab + (size_t)row * KCAT + k0 + half * 16;
    const __nv_bfloat16* gb = Bb + (size_t)row * KCAT + k0 + half * 16;
#pragma unroll
    for (int c = 0; c < 2; c++) {
        int chunk = half * 2 + c;
        int sw = chunk ^ ((row >> 1) & 3);
        CP_ASYNC16(sAdst + row * 64 + sw * 16, ga + c * 8);
        CP_ASYNC16(sBdst + row * 64 + sw * 16, gb + c * 8);
    }
}

__global__ __launch_bounds__(256, 2) void hmma_gemm(
    const __nv_bfloat16* __restrict__ A, const __nv_bfloat16* __restrict__ B,
    const float* __restrict__ bias, float* __restrict__ C, int ldc)
{
    __shared__ __align__(16) __nv_bfloat16 sA[2][128 * 32];
    __shared__ __align__(16) __nv_bfloat16 sB[2][128 * 32];

    const int t = threadIdx.x, wid = t >> 5, lane = t & 31;
    const int bm = blockIdx.y, bn = blockIdx.x;
    const __nv_bfloat16* Ab = A + (size_t)bm * 128 * KCAT;
    const __nv_bfloat16* Bb = B + (size_t)bn * 128 * KCAT;
    const uint32_t sA0 = smem_u32(sA), sB0 = smem_u32(sB);
    const int wm = (wid >> 2) * 64, wn = (wid & 3) * 32;

    float acc[4][4][4];
#pragma unroll
    for (int mt = 0; mt < 4; mt++)
#pragma unroll
        for (int nt = 0; nt < 4; nt++)
#pragma unroll
            for (int r = 0; r < 4; r++) acc[mt][nt][r] = 0.0f;

    load_stage(Ab, Bb, 0, sA0, sB0, t);
    CP_COMMIT();

    for (int s = 0; s < NSTG; s++) {
        CP_WAIT0();
        __syncthreads();
        if (s + 1 < NSTG) {
            int buf = (s + 1) & 1;
            load_stage(Ab, Bb, (s + 1) * 32, sA0 + buf * 8192, sB0 + buf * 8192, t);
            CP_COMMIT();
        }
        const uint32_t ab = sA0 + (s & 1) * 8192;
        const uint32_t bb = sB0 + (s & 1) * 8192;
#pragma unroll
        for (int h = 0; h < 2; h++) {
            uint32_t a[4][4], b[4][2];
#pragma unroll
            for (int mt = 0; mt < 4; mt++) {
                int row = wm + mt * 16 + (lane & 15);
                int chunk = 2 * h + (lane >> 4);
                int sw = chunk ^ ((row >> 1) & 3);
                ldsm_x4(a[mt], ab + row * 64 + sw * 16);
            }
#pragma unroll
            for (int p = 0; p < 2; p++) {
                int row = wn + p * 16 + ((lane >> 4) << 3) + (lane & 7);
                int chunk = 2 * h + ((lane >> 3) & 1);
                int sw = chunk ^ ((row >> 1) & 3);
                uint32_t r4[4];
                ldsm_x4(r4, bb + row * 64 + sw * 16);
                b[p * 2][0] = r4[0]; b[p * 2][1] = r4[1];
                b[p * 2 + 1][0] = r4[2]; b[p * 2 + 1][1] = r4[3];
            }
#pragma unroll
            for (int mt = 0; mt < 4; mt++)
#pragma unroll
                for (int nt = 0; nt < 4; nt++)
                    mma_bf16(acc[mt][nt], a[mt], b[nt]);
        }
        __syncthreads();
    }

    // epilogue: fp32 + bias
#pragma unroll
    for (int mt = 0; mt < 4; mt++) {
        const int r0 = bm * 128 + wm + mt * 16 + (lane >> 2);
#pragma unroll
        for (int nt = 0; nt < 4; nt++) {
            const int col = bn * 128 + wn + nt * 8 + ((lane & 3) << 1);
            float2 bv = *(const float2*)(bias + col);
            float* p0 = C + (size_t)r0 * ldc + col;
            float2 o0, o1;
            o0.x = acc[mt][nt][0] + bv.x; o0.y = acc[mt][nt][1] + bv.y;
            o1.x = acc[mt][nt][2] + bv.x; o1.y = acc[mt][nt][3] + bv.y;
            *(float2*)p0 = o0;
            *(float2*)(p0 + 8 * (size_t)ldc) = o1;
        }
    }
}

// ---------------------------------------------------------------------------
// fp32 -> cat-split bf16: out row = [hi | ? | ?] with hi duplicated and lo at
// configurable segments. x/att use lo@384, hi2@768; weights use hi2@384, lo@768.
// ---------------------------------------------------------------------------
__global__ __launch_bounds__(256) void cat_split(
    const float4* __restrict__ in, __nv_bfloat16* __restrict__ out,
    int n4, int lo_seg, int hi2_seg)
{
    int idx = blockIdx.x * 256 + threadIdx.x;
    if (idx >= n4) return;
    int row = idx / 96;      // DIMC/4 = 96 float4 per row
    int c4  = idx % 96;
    float4 v = in[idx];
    float f[4] = {v.x, v.y, v.z, v.w};
    __nv_bfloat16 hb[4], lb[4];
#pragma unroll
    for (int k = 0; k < 4; k++) {
        hb[k] = __float2bfloat16(f[k]);
        lb[k] = __float2bfloat16(f[k] - __bfloat162float(hb[k]));
    }
    size_t base = (size_t)row * KCAT + c4 * 4;
    *(uint2*)(out + base)           = *(uint2*)hb;
    *(uint2*)(out + base + hi2_seg) = *(uint2*)hb;
    *(uint2*)(out + base + lo_seg)  = *(uint2*)lb;
}

// ---------------------------------------------------------------------------
// Expand rel-pos bias table -> biasx[h][i][j]
// ---------------------------------------------------------------------------
__global__ __launch_bounds__(256) void build_biasx(const float* __restrict__ bt)
{
    int idx = blockIdx.x * 256 + threadIdx.x;
    if (idx >= NHEAD * NTOK * NTOK) return;
    int h = idx >> 12;
    int i = (idx >> 6) & 63;
    int j = idx & 63;
    int ri = i >> 3, ci = i & 7, rj = j >> 3, cj = j & 7;
    g_biasx[idx] = bt[((ri - rj + 7) * 15 + (ci - cj + 7)) * 12 + h];
}

// ---------------------------------------------------------------------------
// Window attention: softmax(q k^T * scale + bias) v, per (window, head).
// 64 threads (thread = query row). q in regs; k,v in smem; bias from L2.
// Writes cat-split bf16 output directly (feeds proj GEMM).
// ---------------------------------------------------------------------------
__global__ __launch_bounds__(64) void attn_kernel()
{
    const int b = blockIdx.x, h = blockIdx.y, i = threadIdx.x;

    __shared__ float k_s[64][32];
    __shared__ float v_s[64][32];

    const float* qkvw = g_qkv + (size_t)b * NTOK * QKVD;
#pragma unroll
    for (int r = 0; r < 32; r++) {
        int e = r * 64 + i;
        int j = e >> 5, d = e & 31;
        k_s[j][d] = qkvw[(size_t)j * QKVD + DIMC + h * HEADD + d];
        v_s[j][d] = qkvw[(size_t)j * QKVD + 2 * DIMC + h * HEADD + d];
    }

    const float scale = 0.17677669529663687f;   // 32^-0.5
    float qi[32];
    const float* qrow = qkvw + (size_t)i * QKVD + h * HEADD;
#pragma unroll
    for (int d = 0; d < 32; d += 4) {
        float4 v = *(const float4*)(qrow + d);
        qi[d] = v.x * scale; qi[d + 1] = v.y * scale;
        qi[d + 2] = v.z * scale; qi[d + 3] = v.w * scale;
    }
    __syncthreads();

    const float* brow = g_biasx + ((size_t)h * NTOK + i) * NTOK;

    float s[64];
    float mx = -INFINITY;
#pragma unroll
    for (int j4 = 0; j4 < 16; j4++) {
        float4 bv = *(const float4*)(brow + j4 * 4);
        float bj[4] = {bv.x, bv.y, bv.z, bv.w};
#pragma unroll
        for (int u = 0; u < 4; u++) {
            int j = j4 * 4 + u;
            float acc = bj[u];
#pragma unroll
            for (int d = 0; d < 32; d++) acc += qi[d] * k_s[j][d];
            s[j] = acc;
            mx = fmaxf(mx, acc);
        }
    }

    float sum = 0.0f;
#pragma unroll
    for (int j = 0; j < 64; j++) { s[j] = __expf(s[j] - mx); sum += s[j]; }
    const float inv = 1.0f / sum;

    // output row i, in 8-wide chunks; write cat-split bf16 directly
    __nv_bfloat16* orow = g_acat + (size_t)(b * NTOK + i) * KCAT + h * HEADD;
#pragma unroll
    for (int d0 = 0; d0 < 4; d0++) {
        float o[8];
#pragma unroll
        for (int u = 0; u < 8; u++) o[u] = 0.0f;
#pragma unroll
        for (int j = 0; j < 64; j++) {
            float sj = s[j];
#pragma unroll
            for (int u = 0; u < 8; u++) o[u] += sj * v_s[j][d0 * 8 + u];
        }
        __nv_bfloat16 hb[8], lb[8];
#pragma unroll
        for (int u = 0; u < 8; u++) {
            float v = o[u] * inv;
            hb[u] = __float2bfloat16(v);
            lb[u] = __float2bfloat16(v - __bfloat162float(hb[u]));
        }
        *(uint4*)(orow + d0 * 8)       = *(uint4*)hb;   // hi  @ k
        *(uint4*)(orow + 768 + d0 * 8) = *(uint4*)hb;   // hi  @ k+768
        *(uint4*)(orow + 384 + d0 * 8) = *(uint4*)lb;   // lo  @ k+384
    }
}

// ---------------------------------------------------------------------------
// Launch. Inputs: x, qkv_w, qkv_b, proj_w, proj_b, bias_table
// ---------------------------------------------------------------------------
extern "C" void kernel_launch(void* const* d_in, const int* in_sizes, int n_in,
                              void* d_out, int out_size)
{
    const float* x          = (const float*)d_in[0];
    const float* qkv_w      = (const float*)d_in[1];
    const float* qkv_b      = (const float*)d_in[2];
    const float* proj_w     = (const float*)d_in[3];
    const float* proj_b     = (const float*)d_in[4];
    const float* bias_table = (const float*)d_in[5];
    float* out = (float*)d_out;

    float* qkv_p;
    __nv_bfloat16 *xcat, *acat, *wqcat, *wpcat;
    cudaGetSymbolAddress((void**)&qkv_p, g_qkv);
    cudaGetSymbolAddress((void**)&xcat, g_xcat);
    cudaGetSymbolAddress((void**)&acat, g_acat);
    cudaGetSymbolAddress((void**)&wqcat, g_wqcat);
    cudaGetSymbolAddress((void**)&wpcat, g_wpcat);

    // bias expansion + cat-splits
    build_biasx<<<(NHEAD * NTOK * NTOK + 255) / 256, 256>>>(bias_table);
    {
        int n4 = MTOT * DIMC / 4;
        cat_split<<<(n4 + 255) / 256, 256>>>((const float4*)x, xcat, n4, 384, 768);
    }
    {
        int n4 = QKVD * DIMC / 4;
        cat_split<<<(n4 + 255) / 256, 256>>>((const float4*)qkv_w, wqcat, n4, 768, 384);
    }
    {
        int n4 = DIMC * DIMC / 4;
        cat_split<<<(n4 + 255) / 256, 256>>>((const float4*)proj_w, wpcat, n4, 768, 384);
    }

    // 1) QKV GEMM: [262144,1152] = xcat @ wqcat^T + b
    {
        dim3 grid(QKVD / 128, MTOT / 128);   // (9, 2048)
        hmma_gemm<<<grid, 256>>>(xcat, wqcat, qkv_b, qkv_p, QKVD);
    }

    // 2) attention (writes cat-split att)
    {
        dim3 grid(BN_WIN, NHEAD);
        attn_kernel<<<grid, 64>>>();
    }

    // 3) proj GEMM: out = acat @ wpcat^T + b
    {
        dim3 grid(DIMC / 128, MTOT / 128);   // (3, 2048)
        hmma_gemm<<<grid, 256>>>(acat, wpcat, proj_b, out, DIMC);
    }
}

// round 5
// speedup vs baseline: 3.8514x; 1.8162x over previous
#include <cuda_runtime.h>
#include <cuda_fp16.h>
#include <cstdint>
#include <math.h>

#define BN_WIN 4096
#define NTOK   64
#define DIMC   384
#define NHEAD  12
#define HEADD  32
#define QKVD   1152
#define MTOT   (BN_WIN * NTOK)   // 262144

// ---------------- scratch (device globals) ----------------------------------
__device__ float  g_qkv[(size_t)MTOT * QKVD];     // fp32 QKV (1.2 GB)
__device__ __half g_xh[(size_t)MTOT * DIMC];      // fp16 x
__device__ __half g_ah[(size_t)MTOT * DIMC];      // fp16 attention out
__device__ __half g_wqh[QKVD * DIMC];
__device__ __half g_wph[DIMC * DIMC];
__device__ float  g_biasx[NHEAD * NTOK * NTOK];   // expanded rel-pos bias

// ---------------- helpers ----------------------------------------------------
__device__ __forceinline__ uint32_t smem_u32(const void* p) {
    uint32_t a;
    asm("{ .reg .u64 t; cvta.to.shared.u64 t, %1; cvt.u32.u64 %0, t; }" : "=r"(a) : "l"(p));
    return a;
}
__device__ __forceinline__ void ldsm_x4(uint32_t* r, uint32_t addr) {
    asm volatile("ldmatrix.sync.aligned.m8n8.x4.shared.b16 {%0,%1,%2,%3}, [%4];"
        : "=r"(r[0]), "=r"(r[1]), "=r"(r[2]), "=r"(r[3]) : "r"(addr));
}
__device__ __forceinline__ void mma_f16(float* d, const uint32_t* a, const uint32_t* b) {
    asm volatile("mma.sync.aligned.m16n8k16.row.col.f32.f16.f16.f32 "
        "{%0,%1,%2,%3}, {%4,%5,%6,%7}, {%8,%9}, {%0,%1,%2,%3};"
        : "+f"(d[0]), "+f"(d[1]), "+f"(d[2]), "+f"(d[3])
        : "r"(a[0]), "r"(a[1]), "r"(a[2]), "r"(a[3]), "r"(b[0]), "r"(b[1]));
}
#define CP_ASYNC16(dst, src) \
    asm volatile("cp.async.cg.shared.global [%0], [%1], 16;" :: "r"(dst), "l"(src) : "memory")
#define CP_COMMIT()  asm volatile("cp.async.commit_group;" ::: "memory")
#define CP_WAIT0()   asm volatile("cp.async.wait_group 0;" ::: "memory")

// packed fp32x2 (Blackwell base ISA, PTX 8.6+)
__device__ __forceinline__ void fma2(uint64_t& acc, uint64_t a, uint64_t b) {
    asm("fma.rn.f32x2 %0, %1, %2, %0;" : "+l"(acc) : "l"(a), "l"(b));
}
__device__ __forceinline__ uint64_t pack2(float lo, float hi) {
    uint64_t r; asm("mov.b64 %0, {%1, %2};" : "=l"(r) : "f"(lo), "f"(hi)); return r;
}
__device__ __forceinline__ void unpack2(uint64_t v, float& lo, float& hi) {
    asm("mov.b64 {%0, %1}, %2;" : "=f"(lo), "=f"(hi) : "l"(v));
}

// ---------------------------------------------------------------------------
// HMMA NT GEMM (fp16): C[M,N] = A[M,K] @ B[N,K]^T + bias[N], fp32 out
// Block 128x128, 8 warps (2x4, warp tile 64x32), k-step 32, double-buffered
// cp.async, XOR-swizzled smem. grid.x = N/128, grid.y = M/128. K % 32 == 0.
// ---------------------------------------------------------------------------
__device__ __forceinline__ void load_stage(
    const __half* Ab, const __half* Bb, int K, int k0,
    uint32_t sAdst, uint32_t sBdst, int t)
{
    const int row  = t >> 1;
    const int half = t & 1;
    const __half* ga = Ab + (size_t)row * K + k0 + half * 16;
    const __half* gb = Bb + (size_t)row * K + k0 + half * 16;
#pragma unroll
    for (int c = 0; c < 2; c++) {
        int chunk = half * 2 + c;
        int sw = chunk ^ ((row >> 1) & 3);
        CP_ASYNC16(sAdst + row * 64 + sw * 16, ga + c * 8);
        CP_ASYNC16(sBdst + row * 64 + sw * 16, gb + c * 8);
    }
}

__global__ __launch_bounds__(256, 2) void hmma_gemm(
    const __half* __restrict__ A, const __half* __restrict__ B,
    const float* __restrict__ bias, float* __restrict__ C, int K, int ldc)
{
    __shared__ __align__(16) __half sA[2][128 * 32];
    __shared__ __align__(16) __half sB[2][128 * 32];

    const int t = threadIdx.x, wid = t >> 5, lane = t & 31;
    const int bm = blockIdx.y, bn = blockIdx.x;
    const __half* Ab = A + (size_t)bm * 128 * K;
    const __half* Bb = B + (size_t)bn * 128 * K;
    const uint32_t sA0 = smem_u32(sA), sB0 = smem_u32(sB);
    const int wm = (wid >> 2) * 64, wn = (wid & 3) * 32;
    const int nstg = K >> 5;

    float acc[4][4][4];
#pragma unroll
    for (int mt = 0; mt < 4; mt++)
#pragma unroll
        for (int nt = 0; nt < 4; nt++)
#pragma unroll
            for (int r = 0; r < 4; r++) acc[mt][nt][r] = 0.0f;

    load_stage(Ab, Bb, K, 0, sA0, sB0, t);
    CP_COMMIT();

    for (int s = 0; s < nstg; s++) {
        CP_WAIT0();
        __syncthreads();
        if (s + 1 < nstg) {
            int buf = (s + 1) & 1;
            load_stage(Ab, Bb, K, (s + 1) * 32, sA0 + buf * 8192, sB0 + buf * 8192, t);
            CP_COMMIT();
        }
        const uint32_t ab = sA0 + (s & 1) * 8192;
        const uint32_t bb = sB0 + (s & 1) * 8192;
#pragma unroll
        for (int h = 0; h < 2; h++) {
            uint32_t a[4][4], b[4][2];
#pragma unroll
            for (int mt = 0; mt < 4; mt++) {
                int row = wm + mt * 16 + (lane & 15);
                int chunk = 2 * h + (lane >> 4);
                int sw = chunk ^ ((row >> 1) & 3);
                ldsm_x4(a[mt], ab + row * 64 + sw * 16);
            }
#pragma unroll
            for (int p = 0; p < 2; p++) {
                int row = wn + p * 16 + ((lane >> 4) << 3) + (lane & 7);
                int chunk = 2 * h + ((lane >> 3) & 1);
                int sw = chunk ^ ((row >> 1) & 3);
                uint32_t r4[4];
                ldsm_x4(r4, bb + row * 64 + sw * 16);
                b[p * 2][0] = r4[0]; b[p * 2][1] = r4[1];
                b[p * 2 + 1][0] = r4[2]; b[p * 2 + 1][1] = r4[3];
            }
#pragma unroll
            for (int mt = 0; mt < 4; mt++)
#pragma unroll
                for (int nt = 0; nt < 4; nt++)
                    mma_f16(acc[mt][nt], a[mt], b[nt]);
        }
        __syncthreads();
    }

#pragma unroll
    for (int mt = 0; mt < 4; mt++) {
        const int r0 = bm * 128 + wm + mt * 16 + (lane >> 2);
#pragma unroll
        for (int nt = 0; nt < 4; nt++) {
            const int col = bn * 128 + wn + nt * 8 + ((lane & 3) << 1);
            float2 bv = *(const float2*)(bias + col);
            float* p0 = C + (size_t)r0 * ldc + col;
            float2 o0, o1;
            o0.x = acc[mt][nt][0] + bv.x; o0.y = acc[mt][nt][1] + bv.y;
            o1.x = acc[mt][nt][2] + bv.x; o1.y = acc[mt][nt][3] + bv.y;
            *(float2*)p0 = o0;
            *(float2*)(p0 + 8 * (size_t)ldc) = o1;
        }
    }
}

// ---------------------------------------------------------------------------
// fp32 -> fp16 convert (x4)
// ---------------------------------------------------------------------------
__global__ __launch_bounds__(256) void cvt_half(
    const float4* __restrict__ in, __half* __restrict__ out, int n4)
{
    int i = blockIdx.x * 256 + threadIdx.x;
    if (i >= n4) return;
    float4 v = in[i];
    __half2 a = __floats2half2_rn(v.x, v.y);
    __half2 b = __floats2half2_rn(v.z, v.w);
    uint2 o;
    o.x = *(uint32_t*)&a;
    o.y = *(uint32_t*)&b;
    *(uint2*)(out + (size_t)i * 4) = o;
}

// ---------------------------------------------------------------------------
// Expand rel-pos bias table -> biasx[h][i][j]
// ---------------------------------------------------------------------------
__global__ __launch_bounds__(256) void build_biasx(const float* __restrict__ bt)
{
    int idx = blockIdx.x * 256 + threadIdx.x;
    if (idx >= NHEAD * NTOK * NTOK) return;
    int h = idx >> 12;
    int i = (idx >> 6) & 63;
    int j = idx & 63;
    int ri = i >> 3, ci = i & 7, rj = j >> 3, cj = j & 7;
    g_biasx[idx] = bt[((ri - rj + 7) * 15 + (ci - cj + 7)) * 12 + h];
}

// ---------------------------------------------------------------------------
// Window attention (packed f32x2 math): softmax(q k^T * scale + bias) v
// block = (window, head), 64 threads (thread = query row). Reads fp32 g_qkv,
// writes fp16 g_ah.
// ---------------------------------------------------------------------------
__global__ __launch_bounds__(64) void attn_kernel()
{
    const int b = blockIdx.x, h = blockIdx.y, i = threadIdx.x;

    __shared__ __align__(16) float k_s[64][32];
    __shared__ __align__(16) float v_s[64][32];

    const float* qkvw = g_qkv + (size_t)b * NTOK * QKVD;
#pragma unroll
    for (int r = 0; r < 32; r++) {
        int e = r * 64 + i;
        int j = e >> 5, d = e & 31;
        k_s[j][d] = qkvw[(size_t)j * QKVD + DIMC + h * HEADD + d];
        v_s[j][d] = qkvw[(size_t)j * QKVD + 2 * DIMC + h * HEADD + d];
    }

    const float scale = 0.17677669529663687f;   // 32^-0.5
    uint64_t qp[16];
    const float* qrow = qkvw + (size_t)i * QKVD + h * HEADD;
#pragma unroll
    for (int d = 0; d < 8; d++) {
        float4 v = *(const float4*)(qrow + d * 4);
        qp[d * 2]     = pack2(v.x * scale, v.y * scale);
        qp[d * 2 + 1] = pack2(v.z * scale, v.w * scale);
    }
    __syncthreads();

    const float* brow = g_biasx + ((size_t)h * NTOK + i) * NTOK;

    float s[64];
    float mx = -INFINITY;
#pragma unroll
    for (int j4 = 0; j4 < 16; j4++) {
        float4 bv = *(const float4*)(brow + j4 * 4);
        float bj[4] = {bv.x, bv.y, bv.z, bv.w};
#pragma unroll
        for (int u = 0; u < 4; u++) {
            int j = j4 * 4 + u;
            uint64_t acc = 0;   // packed (0.0f, 0.0f)
            const uint64_t* kp = (const uint64_t*)&k_s[j][0];
#pragma unroll
            for (int d2 = 0; d2 < 16; d2++) fma2(acc, qp[d2], kp[d2]);
            float lo, hi;
            unpack2(acc, lo, hi);
            float val = lo + hi + bj[u];
            s[j] = val;
            mx = fmaxf(mx, val);
        }
    }

    float sum = 0.0f;
#pragma unroll
    for (int j = 0; j < 64; j++) { s[j] = __expf(s[j] - mx); sum += s[j]; }
    const float inv = 1.0f / sum;

    uint64_t o2[16];
#pragma unroll
    for (int d2 = 0; d2 < 16; d2++) o2[d2] = 0;
#pragma unroll
    for (int j = 0; j < 64; j++) {
        uint64_t sj = pack2(s[j], s[j]);
        const uint64_t* vp = (const uint64_t*)&v_s[j][0];
#pragma unroll
        for (int d2 = 0; d2 < 16; d2++) fma2(o2[d2], sj, vp[d2]);
    }

    __half hb[32];
#pragma unroll
    for (int d2 = 0; d2 < 16; d2++) {
        float lo, hi;
        unpack2(o2[d2], lo, hi);
        __half2 p = __floats2half2_rn(lo * inv, hi * inv);
        *(__half2*)&hb[d2 * 2] = p;
    }
    __half* orow = g_ah + (size_t)(b * NTOK + i) * DIMC + h * HEADD;
#pragma unroll
    for (int c = 0; c < 4; c++)
        *(uint4*)(orow + c * 8) = *(uint4*)&hb[c * 8];
}

// ---------------------------------------------------------------------------
// Launch. Inputs: x, qkv_w, qkv_b, proj_w, proj_b, bias_table
// ---------------------------------------------------------------------------
extern "C" void kernel_launch(void* const* d_in, const int* in_sizes, int n_in,
                              void* d_out, int out_size)
{
    const float* x          = (const float*)d_in[0];
    const float* qkv_w      = (const float*)d_in[1];
    const float* qkv_b      = (const float*)d_in[2];
    const float* proj_w     = (const float*)d_in[3];
    const float* proj_b     = (const float*)d_in[4];
    const float* bias_table = (const float*)d_in[5];
    float* out = (float*)d_out;

    float* qkv_p;
    __half *xh, *ah, *wqh, *wph;
    cudaGetSymbolAddress((void**)&qkv_p, g_qkv);
    cudaGetSymbolAddress((void**)&xh, g_xh);
    cudaGetSymbolAddress((void**)&ah, g_ah);
    cudaGetSymbolAddress((void**)&wqh, g_wqh);
    cudaGetSymbolAddress((void**)&wph, g_wph);

    build_biasx<<<(NHEAD * NTOK * NTOK + 255) / 256, 256>>>(bias_table);
    {
        int n4 = MTOT * DIMC / 4;
        cvt_half<<<(n4 + 255) / 256, 256>>>((const float4*)x, xh, n4);
    }
    {
        int n4 = QKVD * DIMC / 4;
        cvt_half<<<(n4 + 255) / 256, 256>>>((const float4*)qkv_w, wqh, n4);
    }
    {
        int n4 = DIMC * DIMC / 4;
        cvt_half<<<(n4 + 255) / 256, 256>>>((const float4*)proj_w, wph, n4);
    }

    // 1) QKV GEMM: g_qkv[262144,1152] = xh @ wqh^T + b   (K=384)
    {
        dim3 grid(QKVD / 128, MTOT / 128);   // (9, 2048)
        hmma_gemm<<<grid, 256>>>(xh, wqh, qkv_b, qkv_p, DIMC, QKVD);
    }

    // 2) attention -> fp16 g_ah
    {
        dim3 grid(BN_WIN, NHEAD);
        attn_kernel<<<grid, 64>>>();
    }

    // 3) proj GEMM: out[262144,384] = ah @ wph^T + b   (K=384)
    {
        dim3 grid(DIMC / 128, MTOT / 128);   // (3, 2048)
        hmma_gemm<<<grid, 256>>>(ah, wph, proj_b, out, DIMC, DIMC);
    }
}

// round 6
// speedup vs baseline: 5.7489x; 1.4927x over previous
#include <cuda_runtime.h>
#include <cuda_fp16.h>
#include <cstdint>
#include <math.h>

#define BN_WIN 4096
#define NTOK   64
#define DIMC   384
#define NHEAD  12
#define HEADD  32
#define QKVD   1152
#define MTOT   (BN_WIN * NTOK)   // 262144

// ---------------- scratch (device globals) ----------------------------------
__device__ __half g_qkvh[(size_t)MTOT * QKVD];    // fp16 QKV (600 MB)
__device__ __half g_xh[(size_t)MTOT * DIMC];      // fp16 x
__device__ __half g_ah[(size_t)MTOT * DIMC];      // fp16 attention out
__device__ __half g_wqh[QKVD * DIMC];
__device__ __half g_wph[DIMC * DIMC];
__device__ float  g_biasx[NHEAD * NTOK * NTOK];   // expanded rel-pos bias

// ---------------- helpers ----------------------------------------------------
__device__ __forceinline__ uint32_t smem_u32(const void* p) {
    uint32_t a;
    asm("{ .reg .u64 t; cvta.to.shared.u64 t, %1; cvt.u32.u64 %0, t; }" : "=r"(a) : "l"(p));
    return a;
}
__device__ __forceinline__ void ldsm_x4(uint32_t* r, uint32_t addr) {
    asm volatile("ldmatrix.sync.aligned.m8n8.x4.shared.b16 {%0,%1,%2,%3}, [%4];"
        : "=r"(r[0]), "=r"(r[1]), "=r"(r[2]), "=r"(r[3]) : "r"(addr));
}
__device__ __forceinline__ void ldsm_x4_t(uint32_t* r, uint32_t addr) {
    asm volatile("ldmatrix.sync.aligned.m8n8.x4.trans.shared.b16 {%0,%1,%2,%3}, [%4];"
        : "=r"(r[0]), "=r"(r[1]), "=r"(r[2]), "=r"(r[3]) : "r"(addr));
}
__device__ __forceinline__ void mma_f16(float* d, const uint32_t* a, const uint32_t* b) {
    asm volatile("mma.sync.aligned.m16n8k16.row.col.f32.f16.f16.f32 "
        "{%0,%1,%2,%3}, {%4,%5,%6,%7}, {%8,%9}, {%0,%1,%2,%3};"
        : "+f"(d[0]), "+f"(d[1]), "+f"(d[2]), "+f"(d[3])
        : "r"(a[0]), "r"(a[1]), "r"(a[2]), "r"(a[3]), "r"(b[0]), "r"(b[1]));
}
__device__ __forceinline__ uint32_t pack_h2(float lo, float hi) {
    __half2 p = __floats2half2_rn(lo, hi);
    return *(uint32_t*)&p;
}
#define CP_ASYNC16(dst, src) \
    asm volatile("cp.async.cg.shared.global [%0], [%1], 16;" :: "r"(dst), "l"(src) : "memory")
#define CP_COMMIT()  asm volatile("cp.async.commit_group;" ::: "memory")
#define CP_WAIT0()   asm volatile("cp.async.wait_group 0;" ::: "memory")

// ---------------------------------------------------------------------------
// HMMA NT GEMM (fp16 in): C[M,N] = A[M,K] @ B[N,K]^T + bias[N]
// OutT = float or __half. Block 128x128, 8 warps, k-step 32, double-buffered
// cp.async, XOR-swizzled smem. grid.x = N/128, grid.y = M/128. K % 32 == 0.
// ---------------------------------------------------------------------------
__device__ __forceinline__ void load_stage(
    const __half* Ab, const __half* Bb, int K, int k0,
    uint32_t sAdst, uint32_t sBdst, int t)
{
    const int row  = t >> 1;
    const int half = t & 1;
    const __half* ga = Ab + (size_t)row * K + k0 + half * 16;
    const __half* gb = Bb + (size_t)row * K + k0 + half * 16;
#pragma unroll
    for (int c = 0; c < 2; c++) {
        int chunk = half * 2 + c;
        int sw = chunk ^ ((row >> 1) & 3);
        CP_ASYNC16(sAdst + row * 64 + sw * 16, ga + c * 8);
        CP_ASYNC16(sBdst + row * 64 + sw * 16, gb + c * 8);
    }
}

template <typename OutT>
__global__ __launch_bounds__(256, 2) void hmma_gemm(
    const __half* __restrict__ A, const __half* __restrict__ B,
    const float* __restrict__ bias, OutT* __restrict__ C, int K, int ldc)
{
    __shared__ __align__(16) __half sA[2][128 * 32];
    __shared__ __align__(16) __half sB[2][128 * 32];

    const int t = threadIdx.x, wid = t >> 5, lane = t & 31;
    const int bm = blockIdx.y, bn = blockIdx.x;
    const __half* Ab = A + (size_t)bm * 128 * K;
    const __half* Bb = B + (size_t)bn * 128 * K;
    const uint32_t sA0 = smem_u32(sA), sB0 = smem_u32(sB);
    const int wm = (wid >> 2) * 64, wn = (wid & 3) * 32;
    const int nstg = K >> 5;

    float acc[4][4][4];
#pragma unroll
    for (int mt = 0; mt < 4; mt++)
#pragma unroll
        for (int nt = 0; nt < 4; nt++)
#pragma unroll
            for (int r = 0; r < 4; r++) acc[mt][nt][r] = 0.0f;

    load_stage(Ab, Bb, K, 0, sA0, sB0, t);
    CP_COMMIT();

    for (int s = 0; s < nstg; s++) {
        CP_WAIT0();
        __syncthreads();
        if (s + 1 < nstg) {
            int buf = (s + 1) & 1;
            load_stage(Ab, Bb, K, (s + 1) * 32, sA0 + buf * 8192, sB0 + buf * 8192, t);
            CP_COMMIT();
        }
        const uint32_t ab = sA0 + (s & 1) * 8192;
        const uint32_t bb = sB0 + (s & 1) * 8192;
#pragma unroll
        for (int h = 0; h < 2; h++) {
            uint32_t a[4][4], b[4][2];
#pragma unroll
            for (int mt = 0; mt < 4; mt++) {
                int row = wm + mt * 16 + (lane & 15);
                int chunk = 2 * h + (lane >> 4);
                int sw = chunk ^ ((row >> 1) & 3);
                ldsm_x4(a[mt], ab + row * 64 + sw * 16);
            }
#pragma unroll
            for (int p = 0; p < 2; p++) {
                int row = wn + p * 16 + ((lane >> 4) << 3) + (lane & 7);
                int chunk = 2 * h + ((lane >> 3) & 1);
                int sw = chunk ^ ((row >> 1) & 3);
                uint32_t r4[4];
                ldsm_x4(r4, bb + row * 64 + sw * 16);
                b[p * 2][0] = r4[0]; b[p * 2][1] = r4[1];
                b[p * 2 + 1][0] = r4[2]; b[p * 2 + 1][1] = r4[3];
            }
#pragma unroll
            for (int mt = 0; mt < 4; mt++)
#pragma unroll
                for (int nt = 0; nt < 4; nt++)
                    mma_f16(acc[mt][nt], a[mt], b[nt]);
        }
        __syncthreads();
    }

#pragma unroll
    for (int mt = 0; mt < 4; mt++) {
        const int r0 = bm * 128 + wm + mt * 16 + (lane >> 2);
#pragma unroll
        for (int nt = 0; nt < 4; nt++) {
            const int col = bn * 128 + wn + nt * 8 + ((lane & 3) << 1);
            float2 bv = *(const float2*)(bias + col);
            if constexpr (sizeof(OutT) == 2) {
                __half* p0 = (__half*)C + (size_t)r0 * ldc + col;
                __half2 h0 = __floats2half2_rn(acc[mt][nt][0] + bv.x, acc[mt][nt][1] + bv.y);
                __half2 h1 = __floats2half2_rn(acc[mt][nt][2] + bv.x, acc[mt][nt][3] + bv.y);
                *(__half2*)p0 = h0;
                *(__half2*)(p0 + 8 * (size_t)ldc) = h1;
            } else {
                float* p0 = (float*)C + (size_t)r0 * ldc + col;
                float2 o0, o1;
                o0.x = acc[mt][nt][0] + bv.x; o0.y = acc[mt][nt][1] + bv.y;
                o1.x = acc[mt][nt][2] + bv.x; o1.y = acc[mt][nt][3] + bv.y;
                *(float2*)p0 = o0;
                *(float2*)(p0 + 8 * (size_t)ldc) = o1;
            }
        }
    }
}

// ---------------------------------------------------------------------------
// fp32 -> fp16 convert (x4)
// ---------------------------------------------------------------------------
__global__ __launch_bounds__(256) void cvt_half(
    const float4* __restrict__ in, __half* __restrict__ out, int n4)
{
    int i = blockIdx.x * 256 + threadIdx.x;
    if (i >= n4) return;
    float4 v = in[i];
    __half2 a = __floats2half2_rn(v.x, v.y);
    __half2 b = __floats2half2_rn(v.z, v.w);
    uint2 o;
    o.x = *(uint32_t*)&a;
    o.y = *(uint32_t*)&b;
    *(uint2*)(out + (size_t)i * 4) = o;
}

// ---------------------------------------------------------------------------
// Expand rel-pos bias table -> biasx[h][i][j]
// ---------------------------------------------------------------------------
__global__ __launch_bounds__(256) void build_biasx(const float* __restrict__ bt)
{
    int idx = blockIdx.x * 256 + threadIdx.x;
    if (idx >= NHEAD * NTOK * NTOK) return;
    int h = idx >> 12;
    int i = (idx >> 6) & 63;
    int j = idx & 63;
    int ri = i >> 3, ci = i & 7, rj = j >> 3, cj = j & 7;
    g_biasx[idx] = bt[((ri - rj + 7) * 15 + (ci - cj + 7)) * 12 + h];
}

// ---------------------------------------------------------------------------
// HMMA window attention. Block = (window, 4-head group), 4 warps, 1 warp/head.
// Per warp: S = Q@K^T (HMMA), scale+bias, warp softmax, O = P@V (HMMA, P from
// S fragments, V via ldmatrix.trans). fp16 in (g_qkvh), fp16 out (g_ah).
// ---------------------------------------------------------------------------
__global__ __launch_bounds__(128) void attn_hmma()
{
    __shared__ __align__(16) __half sm[4][3][2048];   // [warp][q/k/v][64*32]

    const int b = blockIdx.x;
    const int w = threadIdx.x >> 5, lane = threadIdx.x & 31;
    const int h = blockIdx.y * 4 + w;

    // ---- load q,k,v tiles for this head into swizzled smem ----
    const __half* src = g_qkvh + (size_t)b * NTOK * QKVD + h * HEADD;
    {
        const int rbase = lane >> 2;       // 0..7
        const int seg   = lane & 3;        // 16B segment
#pragma unroll
        for (int sec = 0; sec < 3; sec++) {
            char* dst = (char*)sm[w][sec];
            const __half* g = src + sec * DIMC + seg * 8;
#pragma unroll
            for (int it = 0; it < 8; it++) {
                int row = it * 8 + rbase;
                uint4 val = *(const uint4*)(g + (size_t)row * QKVD);
                int sw = seg ^ ((row >> 1) & 3);
                *(uint4*)(dst + row * 64 + sw * 16) = val;
            }
        }
    }
    __syncwarp();

    const uint32_t qs = smem_u32(sm[w][0]);
    const uint32_t ks = smem_u32(sm[w][1]);
    const uint32_t vs = smem_u32(sm[w][2]);

    // ---- Q a-frags: [mt][kstep16][4] ----
    uint32_t aq[4][2][4];
#pragma unroll
    for (int mt = 0; mt < 4; mt++)
#pragma unroll
        for (int kd = 0; kd < 2; kd++) {
            int row = mt * 16 + (lane & 15);
            int chunk = kd * 2 + (lane >> 4);
            int sw = chunk ^ ((row >> 1) & 3);
            ldsm_x4(aq[mt][kd], qs + row * 64 + sw * 16);
        }

    // ---- K b-frags: [nt][kstep16][2] ----
    uint32_t bk[8][2][2];
#pragma unroll
    for (int np = 0; np < 4; np++)
#pragma unroll
        for (int kd = 0; kd < 2; kd++) {
            int row = np * 16 + ((lane >> 4) << 3) + (lane & 7);
            int chunk = kd * 2 + ((lane >> 3) & 1);
            int sw = chunk ^ ((row >> 1) & 3);
            uint32_t r4[4];
            ldsm_x4(r4, ks + row * 64 + sw * 16);
            bk[np * 2][kd][0] = r4[0];     bk[np * 2][kd][1] = r4[1];
            bk[np * 2 + 1][kd][0] = r4[2]; bk[np * 2 + 1][kd][1] = r4[3];
        }

    // ---- S = Q @ K^T ----
    float s[4][8][4];
#pragma unroll
    for (int mt = 0; mt < 4; mt++)
#pragma unroll
        for (int nt = 0; nt < 8; nt++) {
            s[mt][nt][0] = s[mt][nt][1] = s[mt][nt][2] = s[mt][nt][3] = 0.0f;
#pragma unroll
            for (int kd = 0; kd < 2; kd++)
                mma_f16(s[mt][nt], aq[mt][kd], bk[nt][kd]);
        }

    // ---- scale + rel-pos bias ----
    const float scale = 0.17677669529663687f;   // 32^-0.5
    const float* bb = g_biasx + (size_t)h * NTOK * NTOK;
    const int rA = lane >> 2, c0 = (lane & 3) * 2;
#pragma unroll
    for (int mt = 0; mt < 4; mt++) {
        int rowA = mt * 16 + rA;
#pragma unroll
        for (int nt = 0; nt < 8; nt++) {
            float2 bA = *(const float2*)(bb + rowA * 64 + nt * 8 + c0);
            float2 bB = *(const float2*)(bb + (rowA + 8) * 64 + nt * 8 + c0);
            s[mt][nt][0] = fmaf(s[mt][nt][0], scale, bA.x);
            s[mt][nt][1] = fmaf(s[mt][nt][1], scale, bA.y);
            s[mt][nt][2] = fmaf(s[mt][nt][2], scale, bB.x);
            s[mt][nt][3] = fmaf(s[mt][nt][3], scale, bB.y);
        }
    }

    // ---- softmax per row (rows spread over lane%4 groups) ----
    float invA[4], invB[4];
#pragma unroll
    for (int mt = 0; mt < 4; mt++) {
        float mA = -1e30f, mB = -1e30f;
#pragma unroll
        for (int nt = 0; nt < 8; nt++) {
            mA = fmaxf(mA, fmaxf(s[mt][nt][0], s[mt][nt][1]));
            mB = fmaxf(mB, fmaxf(s[mt][nt][2], s[mt][nt][3]));
        }
        mA = fmaxf(mA, __shfl_xor_sync(0xffffffffu, mA, 1));
        mA = fmaxf(mA, __shfl_xor_sync(0xffffffffu, mA, 2));
        mB = fmaxf(mB, __shfl_xor_sync(0xffffffffu, mB, 1));
        mB = fmaxf(mB, __shfl_xor_sync(0xffffffffu, mB, 2));
        float sA = 0.0f, sB = 0.0f;
#pragma unroll
        for (int nt = 0; nt < 8; nt++) {
            s[mt][nt][0] = __expf(s[mt][nt][0] - mA);
            s[mt][nt][1] = __expf(s[mt][nt][1] - mA);
            s[mt][nt][2] = __expf(s[mt][nt][2] - mB);
            s[mt][nt][3] = __expf(s[mt][nt][3] - mB);
            sA += s[mt][nt][0] + s[mt][nt][1];
            sB += s[mt][nt][2] + s[mt][nt][3];
        }
        sA += __shfl_xor_sync(0xffffffffu, sA, 1);
        sA += __shfl_xor_sync(0xffffffffu, sA, 2);
        sB += __shfl_xor_sync(0xffffffffu, sB, 1);
        sB += __shfl_xor_sync(0xffffffffu, sB, 2);
        invA[mt] = 1.0f / sA;
        invB[mt] = 1.0f / sB;
    }

    // ---- V b-frags via ldmatrix.trans: [kstep16][nt8][2] ----
    uint32_t bv[4][4][2];
#pragma unroll
    for (int kt = 0; kt < 4; kt++)
#pragma unroll
        for (int np = 0; np < 2; np++) {
            int row = kt * 16 + (lane & 15);
            int chunk = np * 2 + (lane >> 4);
            int sw = chunk ^ ((row >> 1) & 3);
            uint32_t r4[4];
            ldsm_x4_t(r4, vs + row * 64 + sw * 16);
            bv[kt][np * 2][0] = r4[0];     bv[kt][np * 2][1] = r4[1];
            bv[kt][np * 2 + 1][0] = r4[2]; bv[kt][np * 2 + 1][1] = r4[3];
        }

    // ---- O = P @ V, per m-tile; write fp16 ----
    __half* obase = g_ah + (size_t)(b * NTOK) * DIMC + h * HEADD;
#pragma unroll
    for (int mt = 0; mt < 4; mt++) {
        uint32_t p[4][4];
#pragma unroll
        for (int kt = 0; kt < 4; kt++) {
            p[kt][0] = pack_h2(s[mt][2 * kt][0], s[mt][2 * kt][1]);
            p[kt][1] = pack_h2(s[mt][2 * kt][2], s[mt][2 * kt][3]);
            p[kt][2] = pack_h2(s[mt][2 * kt + 1][0], s[mt][2 * kt + 1][1]);
            p[kt][3] = pack_h2(s[mt][2 * kt + 1][2], s[mt][2 * kt + 1][3]);
        }
        float o[4][4];
#pragma unroll
        for (int nt = 0; nt < 4; nt++) {
            o[nt][0] = o[nt][1] = o[nt][2] = o[nt][3] = 0.0f;
#pragma unroll
            for (int kt = 0; kt < 4; kt++)
                mma_f16(o[nt], p[kt], bv[kt][nt]);
        }
        int rowA = mt * 16 + rA;
#pragma unroll
        for (int nt = 0; nt < 4; nt++) {
            int col = nt * 8 + c0;
            __half2 hA = __floats2half2_rn(o[nt][0] * invA[mt], o[nt][1] * invA[mt]);
            __half2 hB = __floats2half2_rn(o[nt][2] * invB[mt], o[nt][3] * invB[mt]);
            *(__half2*)(obase + (size_t)rowA * DIMC + col) = hA;
            *(__half2*)(obase + (size_t)(rowA + 8) * DIMC + col) = hB;
        }
    }
}

// ---------------------------------------------------------------------------
// Launch. Inputs: x, qkv_w, qkv_b, proj_w, proj_b, bias_table
// ---------------------------------------------------------------------------
extern "C" void kernel_launch(void* const* d_in, const int* in_sizes, int n_in,
                              void* d_out, int out_size)
{
    const float* x          = (const float*)d_in[0];
    const float* qkv_w      = (const float*)d_in[1];
    const float* qkv_b      = (const float*)d_in[2];
    const float* proj_w     = (const float*)d_in[3];
    const float* proj_b     = (const float*)d_in[4];
    const float* bias_table = (const float*)d_in[5];
    float* out = (float*)d_out;

    __half *qkvh, *xh, *ah, *wqh, *wph;
    cudaGetSymbolAddress((void**)&qkvh, g_qkvh);
    cudaGetSymbolAddress((void**)&xh, g_xh);
    cudaGetSymbolAddress((void**)&ah, g_ah);
    cudaGetSymbolAddress((void**)&wqh, g_wqh);
    cudaGetSymbolAddress((void**)&wph, g_wph);

    build_biasx<<<(NHEAD * NTOK * NTOK + 255) / 256, 256>>>(bias_table);
    {
        int n4 = MTOT * DIMC / 4;
        cvt_half<<<(n4 + 255) / 256, 256>>>((const float4*)x, xh, n4);
    }
    {
        int n4 = QKVD * DIMC / 4;
        cvt_half<<<(n4 + 255) / 256, 256>>>((const float4*)qkv_w, wqh, n4);
    }
    {
        int n4 = DIMC * DIMC / 4;
        cvt_half<<<(n4 + 255) / 256, 256>>>((const float4*)proj_w, wph, n4);
    }

    // 1) QKV GEMM -> fp16 g_qkvh   (K=384)
    {
        dim3 grid(QKVD / 128, MTOT / 128);   // (9, 2048)
        hmma_gemm<__half><<<grid, 256>>>(xh, wqh, qkv_b, qkvh, DIMC, QKVD);
    }

    // 2) HMMA attention -> fp16 g_ah
    {
        dim3 grid(BN_WIN, NHEAD / 4);        // (4096, 3)
        attn_hmma<<<grid, 128>>>();
    }

    // 3) proj GEMM -> fp32 out   (K=384)
    {
        dim3 grid(DIMC / 128, MTOT / 128);   // (3, 2048)
        hmma_gemm<float><<<grid, 256>>>(ah, wph, proj_b, out, DIMC, DIMC);
    }
}